// round 1
// baseline (speedup 1.0000x reference)
#include <cuda_runtime.h>
#include <math.h>

// Shapes: B=2, C=256, H=W=64 -> HW=4096, DQ=16, x has 2C=512 channels.
#define HW 4096
#define CCH 256

// Scratch (static device allocations — no cudaMalloc allowed)
__device__ float g_q[2 * 2 * 16 * HW];   // [b][s][d][p]
__device__ float g_k[2 * 2 * 16 * HW];   // [b][s][d][p]
__device__ float g_u[2 * CCH * HW];      // [b][d][p]  u = M @ x(512ch) + bu
__device__ float g_M[CCH * 512];         // fused (Wpt * Wv) for both halves
__device__ float g_bu[CCH];              // fused bias (Wpt1+Wpt2)·bv

// ---------------------------------------------------------------------------
// Kernel A: build fused matrices.
//   M[d][e] = sum_m Wpt[d][(e<256 ? m : 256+m)] * Wv[m][e%256]
//   bu[d]   = sum_m (Wpt[d][m] + Wpt[d][256+m]) * bv[m]
// ---------------------------------------------------------------------------
__global__ void kA_fuse(const float* __restrict__ Wpt,
                        const float* __restrict__ Wv,
                        const float* __restrict__ bv) {
    int d = blockIdx.y;                       // 0..255
    int e = blockIdx.x * 256 + threadIdx.x;   // 0..511
    int half = e >> 8;
    int ec = e & 255;
    const float* wrow = Wpt + d * 512 + half * 256;
    float acc = 0.f;
#pragma unroll 8
    for (int m = 0; m < 256; ++m)
        acc = fmaf(wrow[m], Wv[m * 256 + ec], acc);
    g_M[d * 512 + e] = acc;
    if (e == 0) {
        float a2 = 0.f;
        for (int m = 0; m < 256; ++m)
            a2 = fmaf(Wpt[d * 512 + m] + Wpt[d * 512 + 256 + m], bv[m], a2);
        g_bu[d] = a2;
    }
}

// ---------------------------------------------------------------------------
// Kernel B: q,k projections (DQ=16 each) for both streams.
//   q[b][s][d][p] = sum_c Wq[d][c] * x[b][s*256+c][p] + bq[d]
// grid (32 p-tiles, s, b), 128 threads, one p per thread.
// ---------------------------------------------------------------------------
__global__ void __launch_bounds__(128) kB_qk(const float* __restrict__ x,
                                             const float* __restrict__ Wq,
                                             const float* __restrict__ bq,
                                             const float* __restrict__ Wk,
                                             const float* __restrict__ bk) {
    __shared__ float wq[16 * 256];
    __shared__ float wk[16 * 256];
    int t = threadIdx.x;
    for (int i = t; i < 16 * 256; i += 128) {
        wq[i] = Wq[i];
        wk[i] = Wk[i];
    }
    __syncthreads();
    int p = blockIdx.x * 128 + t;
    int s = blockIdx.y, b = blockIdx.z;
    const float* xp = x + ((size_t)b * 512 + s * 256) * HW + p;
    float qa[16], ka[16];
#pragma unroll
    for (int d = 0; d < 16; ++d) { qa[d] = bq[d]; ka[d] = bk[d]; }
#pragma unroll 4
    for (int c = 0; c < 256; ++c) {
        float xv = xp[(size_t)c * HW];
#pragma unroll
        for (int d = 0; d < 16; ++d) {
            qa[d] = fmaf(wq[d * 256 + c], xv, qa[d]);
            ka[d] = fmaf(wk[d * 256 + c], xv, ka[d]);
        }
    }
    float* qdst = g_q + (size_t)(b * 2 + s) * 16 * HW + p;
    float* kdst = g_k + (size_t)(b * 2 + s) * 16 * HW + p;
#pragma unroll
    for (int d = 0; d < 16; ++d) {
        qdst[(size_t)d * HW] = qa[d];
        kdst[(size_t)d * HW] = ka[d];
    }
}

// ---------------------------------------------------------------------------
// Kernel C: u = M @ x(512ch) + bu.  GEMM 256x4096, K=512, per batch.
// grid (64 p-blocks, 4 d-blocks, b), 256 threads, 64x64 tile, 4x4 microtile.
// ---------------------------------------------------------------------------
__global__ void __launch_bounds__(256) kC_u(const float* __restrict__ x) {
    __shared__ __align__(16) float As[16 * 64];  // [e][d]
    __shared__ __align__(16) float Bs[16 * 64];  // [e][p]
    int t = threadIdx.x, tx = t & 15, ty = t >> 4;
    int pb = blockIdx.x * 64, db = blockIdx.y * 64, b = blockIdx.z;
    float acc[4][4];
#pragma unroll
    for (int i = 0; i < 4; ++i)
#pragma unroll
        for (int j = 0; j < 4; ++j) acc[i][j] = 0.f;

    for (int e0 = 0; e0 < 512; e0 += 16) {
        int r = t >> 2, c4 = (t & 3) * 4;
        float4 av = *(const float4*)&g_M[(db + r) * 512 + e0 + c4];
        int rb = t >> 4, p4 = (t & 15) * 4;
        float4 bv4 = *(const float4*)&x[((size_t)b * 512 + e0 + rb) * HW + pb + p4];
        __syncthreads();
        As[(c4 + 0) * 64 + r] = av.x;
        As[(c4 + 1) * 64 + r] = av.y;
        As[(c4 + 2) * 64 + r] = av.z;
        As[(c4 + 3) * 64 + r] = av.w;
        *(float4*)&Bs[rb * 64 + p4] = bv4;
        __syncthreads();
#pragma unroll
        for (int e = 0; e < 16; ++e) {
            float4 a = *(const float4*)&As[e * 64 + ty * 4];
            float4 bb = *(const float4*)&Bs[e * 64 + tx * 4];
            acc[0][0] = fmaf(a.x, bb.x, acc[0][0]);
            acc[0][1] = fmaf(a.x, bb.y, acc[0][1]);
            acc[0][2] = fmaf(a.x, bb.z, acc[0][2]);
            acc[0][3] = fmaf(a.x, bb.w, acc[0][3]);
            acc[1][0] = fmaf(a.y, bb.x, acc[1][0]);
            acc[1][1] = fmaf(a.y, bb.y, acc[1][1]);
            acc[1][2] = fmaf(a.y, bb.z, acc[1][2]);
            acc[1][3] = fmaf(a.y, bb.w, acc[1][3]);
            acc[2][0] = fmaf(a.z, bb.x, acc[2][0]);
            acc[2][1] = fmaf(a.z, bb.y, acc[2][1]);
            acc[2][2] = fmaf(a.z, bb.z, acc[2][2]);
            acc[2][3] = fmaf(a.z, bb.w, acc[2][3]);
            acc[3][0] = fmaf(a.w, bb.x, acc[3][0]);
            acc[3][1] = fmaf(a.w, bb.y, acc[3][1]);
            acc[3][2] = fmaf(a.w, bb.z, acc[3][2]);
            acc[3][3] = fmaf(a.w, bb.w, acc[3][3]);
        }
    }
#pragma unroll
    for (int dd = 0; dd < 4; ++dd) {
        int d = db + ty * 4 + dd;
        float bias = g_bu[d];
        float4 o;
        o.x = acc[dd][0] + bias;
        o.y = acc[dd][1] + bias;
        o.z = acc[dd][2] + bias;
        o.w = acc[dd][3] + bias;
        *(float4*)&g_u[((size_t)b * CCH + d) * HW + pb + tx * 4] = o;
    }
}

// ---------------------------------------------------------------------------
// Kernel D: flash attention + epilogue.
// Per (b,s): P = softmax_j(Q^T K), O = u @ P^T; out = gamma*(O + bpt) + x.
// grid (64 i-blocks, 4 c-blocks, 4 b*s), 256 threads.
// Tiles: 64 queries x 64 channels accum; loop j in blocks of 64.
// S phase mapping: i = ty*4+ii (row group = half-warp), j = tx*4+jj.
// Apply phase mapping: c = ty*4+cc, i = tx*4+ii.
// ---------------------------------------------------------------------------
__global__ void __launch_bounds__(256) kD_attn(const float* __restrict__ x,
                                               const float* __restrict__ bpt,
                                               const float* __restrict__ gamma,
                                               float* __restrict__ out) {
    __shared__ __align__(16) float Qs[16 * 64];
    __shared__ __align__(16) float Ks[16 * 64];
    __shared__ __align__(16) float Us[64 * 68];  // padded stride 68 (bank-safe)
    __shared__ __align__(16) float Ps[64 * 68];  // [j][i], stride 68
    __shared__ __align__(16) float m_s[64];
    __shared__ __align__(16) float l_s[64];
    __shared__ __align__(16) float sc_s[64];

    int t = threadIdx.x, tx = t & 15, ty = t >> 4;
    int iblk = blockIdx.x, cblk = blockIdx.y, bs = blockIdx.z;
    int b = bs >> 1, s = bs & 1;
    const float* qsrc = g_q + (size_t)bs * 16 * HW + iblk * 64;
    const float* ksrc = g_k + (size_t)bs * 16 * HW;
    const float* usrc = g_u + ((size_t)b * CCH + cblk * 64) * HW;

    // Q tile (16 x 64)
    *(float4*)&Qs[ty * 64 + tx * 4] = *(const float4*)&qsrc[(size_t)ty * HW + tx * 4];
    if (t < 64) { m_s[t] = -1e30f; l_s[t] = 0.f; }

    float acc[4][4];
#pragma unroll
    for (int i = 0; i < 4; ++i)
#pragma unroll
        for (int j = 0; j < 4; ++j) acc[i][j] = 0.f;

    for (int j0 = 0; j0 < HW; j0 += 64) {
        // load K tile (16x64) + U tile (64x64)
        *(float4*)&Ks[ty * 64 + tx * 4] =
            *(const float4*)&ksrc[(size_t)ty * HW + j0 + tx * 4];
#pragma unroll
        for (int rr = 0; rr < 4; ++rr) {
            int r = ty + 16 * rr;
            *(float4*)&Us[r * 68 + tx * 4] =
                *(const float4*)&usrc[(size_t)r * HW + j0 + tx * 4];
        }
        __syncthreads();

        // S = Q^T K  (64i x 64j, inner d=16)
        float sv[4][4];
#pragma unroll
        for (int i = 0; i < 4; ++i)
#pragma unroll
            for (int j = 0; j < 4; ++j) sv[i][j] = 0.f;
#pragma unroll
        for (int d = 0; d < 16; ++d) {
            float4 q = *(const float4*)&Qs[d * 64 + ty * 4];
            float4 k = *(const float4*)&Ks[d * 64 + tx * 4];
            sv[0][0] = fmaf(q.x, k.x, sv[0][0]);
            sv[0][1] = fmaf(q.x, k.y, sv[0][1]);
            sv[0][2] = fmaf(q.x, k.z, sv[0][2]);
            sv[0][3] = fmaf(q.x, k.w, sv[0][3]);
            sv[1][0] = fmaf(q.y, k.x, sv[1][0]);
            sv[1][1] = fmaf(q.y, k.y, sv[1][1]);
            sv[1][2] = fmaf(q.y, k.z, sv[1][2]);
            sv[1][3] = fmaf(q.y, k.w, sv[1][3]);
            sv[2][0] = fmaf(q.z, k.x, sv[2][0]);
            sv[2][1] = fmaf(q.z, k.y, sv[2][1]);
            sv[2][2] = fmaf(q.z, k.z, sv[2][2]);
            sv[2][3] = fmaf(q.z, k.w, sv[2][3]);
            sv[3][0] = fmaf(q.w, k.x, sv[3][0]);
            sv[3][1] = fmaf(q.w, k.y, sv[3][1]);
            sv[3][2] = fmaf(q.w, k.z, sv[3][2]);
            sv[3][3] = fmaf(q.w, k.w, sv[3][3]);
        }

        // online softmax per row (row group = 16 lanes of a half-warp)
#pragma unroll
        for (int ii = 0; ii < 4; ++ii) {
            int i = ty * 4 + ii;
            float mx = fmaxf(fmaxf(sv[ii][0], sv[ii][1]), fmaxf(sv[ii][2], sv[ii][3]));
#pragma unroll
            for (int off = 8; off; off >>= 1)
                mx = fmaxf(mx, __shfl_xor_sync(0xffffffffu, mx, off, 16));
            float mold = m_s[i];
            float mnew = fmaxf(mold, mx);
            float p0 = __expf(sv[ii][0] - mnew);
            float p1 = __expf(sv[ii][1] - mnew);
            float p2 = __expf(sv[ii][2] - mnew);
            float p3 = __expf(sv[ii][3] - mnew);
            sv[ii][0] = p0; sv[ii][1] = p1; sv[ii][2] = p2; sv[ii][3] = p3;
            float rs = p0 + p1 + p2 + p3;
#pragma unroll
            for (int off = 8; off; off >>= 1)
                rs += __shfl_xor_sync(0xffffffffu, rs, off, 16);
            float scale = __expf(mold - mnew);
            float lnew = l_s[i] * scale + rs;
            __syncwarp();
            if (tx == 0) { m_s[i] = mnew; l_s[i] = lnew; sc_s[i] = scale; }
        }
        // write P as [j][i] so apply phase reads contiguous i
#pragma unroll
        for (int jj = 0; jj < 4; ++jj) {
            float4 pv = make_float4(sv[0][jj], sv[1][jj], sv[2][jj], sv[3][jj]);
            *(float4*)&Ps[(tx * 4 + jj) * 68 + ty * 4] = pv;
        }
        __syncthreads();

        // rescale accumulators (i = tx*4+ii), then O += U * P^T
        float s0 = sc_s[tx * 4 + 0];
        float s1 = sc_s[tx * 4 + 1];
        float s2 = sc_s[tx * 4 + 2];
        float s3 = sc_s[tx * 4 + 3];
#pragma unroll
        for (int cc = 0; cc < 4; ++cc) {
            acc[cc][0] *= s0; acc[cc][1] *= s1;
            acc[cc][2] *= s2; acc[cc][3] *= s3;
        }
#pragma unroll 8
        for (int j = 0; j < 64; ++j) {
            float4 pv = *(const float4*)&Ps[j * 68 + tx * 4];
            float u0 = Us[(ty * 4 + 0) * 68 + j];
            float u1 = Us[(ty * 4 + 1) * 68 + j];
            float u2 = Us[(ty * 4 + 2) * 68 + j];
            float u3 = Us[(ty * 4 + 3) * 68 + j];
            acc[0][0] = fmaf(u0, pv.x, acc[0][0]);
            acc[0][1] = fmaf(u0, pv.y, acc[0][1]);
            acc[0][2] = fmaf(u0, pv.z, acc[0][2]);
            acc[0][3] = fmaf(u0, pv.w, acc[0][3]);
            acc[1][0] = fmaf(u1, pv.x, acc[1][0]);
            acc[1][1] = fmaf(u1, pv.y, acc[1][1]);
            acc[1][2] = fmaf(u1, pv.z, acc[1][2]);
            acc[1][3] = fmaf(u1, pv.w, acc[1][3]);
            acc[2][0] = fmaf(u2, pv.x, acc[2][0]);
            acc[2][1] = fmaf(u2, pv.y, acc[2][1]);
            acc[2][2] = fmaf(u2, pv.z, acc[2][2]);
            acc[2][3] = fmaf(u2, pv.w, acc[2][3]);
            acc[3][0] = fmaf(u3, pv.x, acc[3][0]);
            acc[3][1] = fmaf(u3, pv.y, acc[3][1]);
            acc[3][2] = fmaf(u3, pv.z, acc[3][2]);
            acc[3][3] = fmaf(u3, pv.w, acc[3][3]);
        }
        __syncthreads();
    }

    // epilogue: out[b][s*256+c][p] = gamma*(O/l + bpt[c]) + x[b][s*256+c][p]
    float li0 = 1.f / l_s[tx * 4 + 0];
    float li1 = 1.f / l_s[tx * 4 + 1];
    float li2 = 1.f / l_s[tx * 4 + 2];
    float li3 = 1.f / l_s[tx * 4 + 3];
    float g = gamma[0];
#pragma unroll
    for (int cc = 0; cc < 4; ++cc) {
        int c = cblk * 64 + ty * 4 + cc;
        int ch = s * 256 + c;
        float bias = bpt[c];
        size_t base = ((size_t)b * 512 + ch) * HW + iblk * 64 + tx * 4;
        float4 xr = *(const float4*)&x[base];
        float4 o;
        o.x = fmaf(g, fmaf(acc[cc][0], li0, bias), xr.x);
        o.y = fmaf(g, fmaf(acc[cc][1], li1, bias), xr.y);
        o.z = fmaf(g, fmaf(acc[cc][2], li2, bias), xr.z);
        o.w = fmaf(g, fmaf(acc[cc][3], li3, bias), xr.w);
        *(float4*)&out[base] = o;
    }
}

// ---------------------------------------------------------------------------
extern "C" void kernel_launch(void* const* d_in, const int* in_sizes, int n_in,
                              void* d_out, int out_size) {
    const float* x     = (const float*)d_in[0];
    const float* Wq    = (const float*)d_in[1];
    const float* bq    = (const float*)d_in[2];
    const float* Wk    = (const float*)d_in[3];
    const float* bk    = (const float*)d_in[4];
    const float* Wv    = (const float*)d_in[5];
    const float* bv    = (const float*)d_in[6];
    const float* Wpt   = (const float*)d_in[7];
    const float* bpt   = (const float*)d_in[8];
    const float* gamma = (const float*)d_in[9];
    float* out = (float*)d_out;

    kA_fuse<<<dim3(2, 256), 256>>>(Wpt, Wv, bv);
    kB_qk<<<dim3(32, 2, 2), 128>>>(x, Wq, bq, Wk, bk);
    kC_u<<<dim3(64, 4, 2), 256>>>(x);
    kD_attn<<<dim3(64, 4, 4), 256>>>(x, bpt, gamma, out);
}